// round 9
// baseline (speedup 1.0000x reference)
#include <cuda_runtime.h>
#include <math.h>

#define BATCH 256
#define NSTEP 32
#define NIMG  (BATCH*NSTEP)

#define GUARD_BASE 81920
#define STATE_BASE 131072

typedef unsigned long long u64t;

// packed f32x2 helpers
#define PACK2(d, lo, hi) \
    asm("mov.b64 %0, {%1, %2};" : "=l"(d) : "r"(__float_as_uint(lo)), "r"(__float_as_uint(hi)))
#define FMA2(d, a, b, c) \
    asm("fma.rn.f32x2 %0, %1, %2, %3;" : "=l"(d) : "l"(a), "l"(b), "l"(c))
#define ADD2(d, a, b) \
    asm("add.rn.f32x2 %0, %1, %2;" : "=l"(d) : "l"(a), "l"(b))
#define MUL2(d, a, b) \
    asm("mul.rn.f32x2 %0, %1, %2;" : "=l"(d) : "l"(a), "l"(b))
#define ABS2(d, s) \
    asm("and.b64 %0, %1, 0x7FFFFFFF7FFFFFFF;" : "=l"(d) : "l"(s))

// 6 FMA2s of one input row into two dx-accumulators, cached-weight form
#define ROW6(a0, a1, wb) \
    FMA2(a0, row0, wk[(wb)+0], a0); FMA2(a0, row1, wk[(wb)+1], a0); \
    FMA2(a0, row2, wk[(wb)+2], a0); \
    FMA2(a1, row1, wk[(wb)+0], a1); FMA2(a1, row2, wk[(wb)+1], a1); \
    FMA2(a1, row3, wk[(wb)+2], a1)

// explicit-weight form (weights transient, not register-cached)
#define ROW6W(a0, a1, w0_, w1_, w2_) \
    FMA2(a0, row0, w0_, a0); FMA2(a0, row1, w1_, a0); FMA2(a0, row2, w2_, a0); \
    FMA2(a1, row1, w0_, a1); FMA2(a1, row2, w1_, a1); FMA2(a1, row3, w2_, a1)

__device__ float g_M[600];                 // (6,10,10) transition matrices
__device__ float g_guardT[BATCH][NSTEP*6]; // transposed guards for sfa

struct SmemLayout {                        // all pair arrays hold (im0, im1)
    u64t imgp[28 * 30];                    // image pairs, row stride 30
    u64t s1pair[8 * 13 * 14];              // pooled conv1 pairs, row stride 14
    u64t s2pair[16 * 26];                  // pooled conv2 pairs
    u64t s3pair[32];
    u64t w1dup[8 * 10];  u64t b1d[8];      // dup'd weights/biases
    u64t w2dup[16 * 8 * 12]; u64t b2d[16]; // weight rows at +0,+4,+8 (16B aligned)
    u64t b3d[32];
    u64t dwdup[32 * 10]; u64t dbd[10];
    u64t logp[10];
    float w3[32 * 16 * 9];                 // conv3 weights, plain
    float p2[2][10];
};

// ---------------------------------------------------------------------------
__global__ __launch_bounds__(256, 4) void cnn_kernel(
    const float* __restrict__ seq,
    const float* __restrict__ c1w, const float* __restrict__ c1b,
    const float* __restrict__ c2w, const float* __restrict__ c2b,
    const float* __restrict__ c3w, const float* __restrict__ c3b,
    const float* __restrict__ dw,  const float* __restrict__ db,
    const float* __restrict__ trans,
    float* __restrict__ out)
{
    extern __shared__ __align__(16) char smem_raw[];
    SmemLayout* S = (SmemLayout*)smem_raw;

    const int tid = threadIdx.x;

    // ---- prep (block 0): transition matrices ----
    if (blockIdx.x == 0 && tid < 60) {
        if (tid < 54) {
            const int r = tid / 9, i = tid - r * 9;
            const float* tp = trans + (r * 9 + i) * 10;
            float m = tp[0] * 10.f;
            #pragma unroll
            for (int j = 1; j < 10; j++) m = fmaxf(m, tp[j] * 10.f);
            float e[10];
            float s = 0.f;
            #pragma unroll
            for (int j = 0; j < 10; j++) { e[j] = __expf(tp[j] * 10.f - m); s += e[j]; }
            const float inv = 1.f / s;
            #pragma unroll
            for (int j = 0; j < 10; j++) g_M[r * 100 + i * 10 + j] = e[j] * inv;
        } else {
            const int r = tid - 54;
            #pragma unroll
            for (int j = 0; j < 10; j++) g_M[r * 100 + 90 + j] = (j == 9) ? 1.f : 0.f;
        }
    }

    // ---- load phase: build image pairs + dup'd weights ----
    {
        const int img0 = blockIdx.x * 2;
        const int n0 = img0 >> 8, b0 = img0 & 255;
        const int img1 = img0 + 1;
        const int n1 = img1 >> 8, b1 = img1 & 255;
        const float* p0 = seq + ((long)b0 * NSTEP + n0) * 784;
        const float* p1 = seq + ((long)b1 * NSTEP + n1) * 784;
        for (int q = tid; q < 392; q += 256) {
            const float2 va = ((const float2*)p0)[q];
            const float2 vb = ((const float2*)p1)[q];
            const int row = q / 14, col2 = q - row * 14;
            u64t lo, hi;
            PACK2(lo, va.x, vb.x);
            PACK2(hi, va.y, vb.y);
            S->imgp[row * 30 + col2 * 2    ] = lo;
            S->imgp[row * 30 + col2 * 2 + 1] = hi;
        }
    }
    if (tid < 8) {
        #pragma unroll
        for (int t = 0; t < 9; t++) {
            u64t d; const float w = c1w[tid * 9 + t];
            PACK2(d, w, w);
            S->w1dup[tid * 10 + t] = d;
        }
        u64t bd; const float bb = c1b[tid];
        PACK2(bd, bb, bb);
        S->b1d[tid] = bd;
    }
    if (tid < 128) {   // weight rows at +0,+4,+8 within stride-12 record
        #pragma unroll
        for (int t = 0; t < 9; t++) {
            u64t d; const float w = c2w[tid * 9 + t];
            PACK2(d, w, w);
            S->w2dup[tid * 12 + (t / 3) * 4 + (t % 3)] = d;
        }
    }
    if (tid < 16) { u64t bd; const float bb = c2b[tid]; PACK2(bd, bb, bb); S->b2d[tid] = bd; }
    for (int k = tid; k < 4608; k += 256) S->w3[k] = c3w[k];
    if (tid < 32) { u64t bd; const float bb = c3b[tid]; PACK2(bd, bb, bb); S->b3d[tid] = bd; }
    for (int k2 = tid; k2 < 320; k2 += 256) {
        const int j = k2 >> 5, k = k2 & 31;
        u64t d; const float w = dw[j * 32 + k];
        PACK2(d, w, w);
        S->dwdup[k * 10 + j] = d;
    }
    if (tid < 10) { u64t bd; const float bb = db[tid]; PACK2(bd, bb, bb); S->dbd[tid] = bd; }
    __syncthreads();

    u64t C0125; PACK2(C0125, 0.125f, 0.125f);

    // ---- Stage 1: conv1 + relu + pool (packed pairs). 208 threads ----
    if (tid < 208) {
        const int c   = tid / 26;
        const int rem = tid - c * 26;
        const int y   = rem >> 1;
        const int xh  = rem & 1;
        const int x0  = xh * 7;
        const int xN  = xh ? 6 : 7;
        const int iy  = 2 * y;

        u64t wk[9];
        {
            const u64t* wp = &S->w1dup[c * 10];
            const ulonglong2 w01 = *(const ulonglong2*)&wp[0];
            const ulonglong2 w23 = *(const ulonglong2*)&wp[2];
            const ulonglong2 w45 = *(const ulonglong2*)&wp[4];
            const ulonglong2 w67 = *(const ulonglong2*)&wp[6];
            wk[0]=w01.x; wk[1]=w01.y; wk[2]=w23.x; wk[3]=w23.y;
            wk[4]=w45.x; wk[5]=w45.y; wk[6]=w67.x; wk[7]=w67.y;
            wk[8]=wp[8];
        }
        const u64t bd = S->b1d[c];

        for (int xi = 0; xi < xN; xi++) {
            const int x = x0 + xi;
            const int ix = 2 * x;
            u64t a0 = bd, a1 = bd, a2 = bd, a3 = bd;
            #pragma unroll
            for (int r = 0; r < 4; r++) {
                const u64t* rp = &S->imgp[(iy + r) * 30 + ix];
                const ulonglong2 r01 = *(const ulonglong2*)&rp[0];
                const ulonglong2 r23 = *(const ulonglong2*)&rp[2];
                const u64t row0 = r01.x, row1 = r01.y, row2 = r23.x, row3 = r23.y;
                if (r == 0)      { ROW6(a0, a1, 0); }
                else if (r == 1) { ROW6(a0, a1, 3); ROW6(a2, a3, 0); }
                else if (r == 2) { ROW6(a0, a1, 6); ROW6(a2, a3, 3); }
                else             { ROW6(a2, a3, 6); }
            }
            u64t s01, s23, ssum, t0, t1, t2, t3, u01, u23, asum, tot, res;
            ADD2(s01, a0, a1); ADD2(s23, a2, a3); ADD2(ssum, s01, s23);
            ABS2(t0, a0); ABS2(t1, a1); ABS2(t2, a2); ABS2(t3, a3);
            ADD2(u01, t0, t1); ADD2(u23, t2, t3); ADD2(asum, u01, u23);
            ADD2(tot, ssum, asum);
            MUL2(res, tot, C0125);
            S->s1pair[c * 182 + y * 14 + x] = res;
        }
    }
    __syncthreads();

    // ---- Stage 2: conv2 + relu + pool (packed), POSITION-OUTER (low regs) ----
    {
        const int oc = tid >> 4;
        const int s  = tid & 15;
        const int np = (s < 9) ? 2 : 1;
        const u64t bd = S->b2d[oc];

        for (int pp = 0; pp < np; pp++) {
            const int p = s + pp * 16;
            const int y = p / 5, x = p - y * 5;
            const int iy = 2 * y, ix = 2 * x;

            u64t a0 = bd, a1 = bd, a2 = bd, a3 = bd;
            #pragma unroll
            for (int ic = 0; ic < 8; ic++) {
                const u64t* wp = &S->w2dup[(oc * 8 + ic) * 12];
                #pragma unroll
                for (int r = 0; r < 4; r++) {
                    const u64t* rp = &S->s1pair[ic * 182 + (iy + r) * 14 + ix];
                    const ulonglong2 r01 = *(const ulonglong2*)&rp[0];
                    const ulonglong2 r23 = *(const ulonglong2*)&rp[2];
                    const u64t row0 = r01.x, row1 = r01.y, row2 = r23.x, row3 = r23.y;
                    if (r <= 2) {          // weight row r -> dy=0 accumulators
                        const ulonglong2 wab = *(const ulonglong2*)&wp[r * 4];
                        const u64t wc = wp[r * 4 + 2];
                        ROW6W(a0, a1, wab.x, wab.y, wc);
                    }
                    if (r >= 1) {          // weight row r-1 -> dy=1 accumulators
                        const ulonglong2 wab = *(const ulonglong2*)&wp[(r - 1) * 4];
                        const u64t wc = wp[(r - 1) * 4 + 2];
                        ROW6W(a2, a3, wab.x, wab.y, wc);
                    }
                }
            }
            u64t s01, s23, ssum, t0, t1, t2, t3, u01, u23, asum, tot, res;
            ADD2(s01, a0, a1); ADD2(s23, a2, a3); ADD2(ssum, s01, s23);
            ABS2(t0, a0); ABS2(t1, a1); ABS2(t2, a2); ABS2(t3, a3);
            ADD2(u01, t0, t1); ADD2(u23, t2, t3); ADD2(asum, u01, u23);
            ADD2(tot, ssum, asum);
            MUL2(res, tot, C0125);
            S->s2pair[oc * 26 + p] = res;
        }
    }
    __syncthreads();

    // ---- Stage 3: conv3 + relu + pool. 256 threads (oc32, pos4, ichalf2) ----
    {
        const int oc  = tid >> 3;
        const int pos = (tid >> 1) & 3;
        const int ich = tid & 1;
        const int dy = pos >> 1, dx = pos & 1;

        u64t acc = 0;
        #pragma unroll
        for (int i = 0; i < 8; i++) {
            const int ic = ich * 8 + i;
            const float* wp = &S->w3[(oc * 16 + ic) * 9];
            const u64t* sp = &S->s2pair[ic * 26 + dy * 5 + dx];
            #pragma unroll
            for (int ky = 0; ky < 3; ky++)
                #pragma unroll
                for (int kx = 0; kx < 3; kx++) {
                    const float w = wp[ky * 3 + kx];
                    u64t wd; PACK2(wd, w, w);
                    FMA2(acc, sp[ky * 5 + kx], wd, acc);
                }
        }
        u64t o = __shfl_xor_sync(0xffffffffu, acc, 1);
        ADD2(acc, acc, o);
        ADD2(acc, acc, S->b3d[oc]);
        u64t ab; ABS2(ab, acc); ADD2(acc, acc, ab);        // 2*relu
        o = __shfl_xor_sync(0xffffffffu, acc, 2); ADD2(acc, acc, o);
        o = __shfl_xor_sync(0xffffffffu, acc, 4); ADD2(acc, acc, o);
        MUL2(acc, acc, C0125);                              // 0.5 * 0.25
        if ((tid & 7) == 0) S->s3pair[oc] = acc;
    }
    __syncthreads();

    // ---- Dense + softmax + guards: warp 0 ----
    if (tid < 32) {
        if (tid < 10) {
            u64t acc = S->dbd[tid];
            #pragma unroll
            for (int k = 0; k < 32; k++)
                FMA2(acc, S->s3pair[k], S->dwdup[k * 10 + tid], acc);
            S->logp[tid] = acc;
        }
        __syncwarp();
        if (tid < 20) {
            const int im = tid / 10, j = tid - im * 10;
            const float* lf = (const float*)S->logp;
            float m = lf[im];
            #pragma unroll
            for (int k = 1; k < 10; k++) m = fmaxf(m, lf[k * 2 + im]);
            float sum = 0.f;
            #pragma unroll
            for (int k = 0; k < 10; k++) sum += __expf(lf[k * 2 + im] - m);
            const float p = __expf(lf[j * 2 + im] - m) / sum;
            S->p2[im][j] = p;
            out[(blockIdx.x * 2 + im) * 10 + j] = p;
        }
        __syncwarp();
        if (tid < 12) {
            const int im = tid / 6, j = tid - im * 6;
            const float* p = S->p2[im];
            float g;
            switch (j) {
                case 0:  g = p[8];         break;
                case 1:  g = p[4] + p[6];  break;
                case 2:  g = p[0] + p[2];  break;
                case 3:  g = p[7] + p[9];  break;
                case 4:  g = p[5];         break;
                default: g = p[1] + p[3];  break;
            }
            const int img = blockIdx.x * 2 + im;
            out[GUARD_BASE + img * 6 + j] = g;
            g_guardT[img & 255][(img >> 8) * 6 + j] = g;
        }
    }
}

// ---------------------------------------------------------------------------
// SFA: 32 blocks x 8 warps; warp handles one batch element, coalesced guards.
// ---------------------------------------------------------------------------
__global__ __launch_bounds__(256) void sfa_kernel(float* __restrict__ out)
{
    __shared__ float s_g[8][NSTEP * 6];

    const int tid  = threadIdx.x;
    const int w    = tid >> 5;
    const int lane = tid & 31;
    const int b    = blockIdx.x * 8 + w;

    #pragma unroll
    for (int k = lane; k < NSTEP * 6; k += 32)
        s_g[w][k] = g_guardT[b][k];

    const int jj = (lane < 10) ? lane : 0;
    float Mr[6][10];
    #pragma unroll
    for (int r = 0; r < 6; r++)
        #pragma unroll
        for (int i = 0; i < 10; i++)
            Mr[r][i] = g_M[r * 100 + i * 10 + jj];
    __syncwarp();

    float st = (lane == 0) ? 1.f : 0.f;
    for (int n = 0; n < NSTEP; n++) {
        const float g0 = s_g[w][n*6+0], g1 = s_g[w][n*6+1], g2 = s_g[w][n*6+2];
        const float g3 = s_g[w][n*6+3], g4 = s_g[w][n*6+4], g5 = s_g[w][n*6+5];
        float a = 0.f;
        #pragma unroll
        for (int i = 0; i < 10; i++) {
            const float si = __shfl_sync(0xffffffff, st, i);
            const float mij = g0 * Mr[0][i] + g1 * Mr[1][i] + g2 * Mr[2][i]
                            + g3 * Mr[3][i] + g4 * Mr[4][i] + g5 * Mr[5][i];
            a += si * mij;
        }
        st = a;
    }
    if (lane < 10) out[STATE_BASE + b * 10 + lane] = st;
}

// ---------------------------------------------------------------------------
extern "C" void kernel_launch(void* const* d_in, const int* in_sizes, int n_in,
                              void* d_out, int out_size)
{
    const float* seq   = (const float*)d_in[0];
    const float* c1w   = (const float*)d_in[1];
    const float* c1b   = (const float*)d_in[2];
    const float* c2w   = (const float*)d_in[3];
    const float* c2b   = (const float*)d_in[4];
    const float* c3w   = (const float*)d_in[5];
    const float* c3b   = (const float*)d_in[6];
    const float* dw    = (const float*)d_in[7];
    const float* db    = (const float*)d_in[8];
    const float* trans = (const float*)d_in[9];
    float* out = (float*)d_out;

    const int smem_bytes = (int)sizeof(SmemLayout);
    cudaFuncSetAttribute(cnn_kernel, cudaFuncAttributeMaxDynamicSharedMemorySize,
                         smem_bytes);

    cnn_kernel<<<NIMG / 2, 256, smem_bytes>>>(seq, c1w, c1b, c2w, c2b,
                                              c3w, c3b, dw, db, trans, out);
    sfa_kernel<<<BATCH / 8, 256>>>(out);
}

// round 10
// speedup vs baseline: 1.5210x; 1.5210x over previous
#include <cuda_runtime.h>
#include <math.h>

#define BATCH 256
#define NSTEP 32
#define NIMG  (BATCH*NSTEP)

#define GUARD_BASE 81920
#define STATE_BASE 131072

#define IMG_STRIDE 30
#define S1_STRIDE  22
#define S1_PLANE   (13 * S1_STRIDE)

typedef unsigned long long u64t;

// packed f32x2 helpers (sm_103a FFMA2 path)
#define PACK2(d, lo, hi) \
    asm("mov.b64 %0, {%1, %2};" : "=l"(d) : "r"(__float_as_uint(lo)), "r"(__float_as_uint(hi)))
#define FMA2(d, a, b, c) \
    asm("fma.rn.f32x2 %0, %1, %2, %3;" : "=l"(d) : "l"(a), "l"(b), "l"(c))
#define UNPACK2(lo, hi, s) do { unsigned _ulo, _uhi; \
    asm("mov.b64 {%0, %1}, %2;" : "=r"(_ulo), "=r"(_uhi) : "l"(s)); \
    lo = __uint_as_float(_ulo); hi = __uint_as_float(_uhi); } while (0)

__device__ float g_M[600];                 // (6,10,10) transition matrices
__device__ float g_guardT[BATCH][NSTEP*6]; // transposed guards for sfa

struct SmemLayout {
    float img[2][28 * IMG_STRIDE];
    float s1p[2][8 * S1_PLANE];
    float s2[2][400];
    float s3[2][32];
    float w1p[8 * 12];  float b1[8];
    float w2pk[8 * 8 * 20];      // [ocpair][ic][k*2+half], padded to 20
    float b2[16];
    float w3pk[8 * 9 * 32 * 2];  // [icpair][k][oc] float2 (ic even, ic odd)
    float b3[32];
    float dwT[32 * 10]; float db[10];
    float logits[2][10]; float p2[2][10];
};

// ---------------------------------------------------------------------------
// Fused CNN, 2 images per CTA, 256 threads (round-6 proven version).
// ---------------------------------------------------------------------------
__global__ __launch_bounds__(256, 4) void cnn_kernel(
    const float* __restrict__ seq,
    const float* __restrict__ c1w, const float* __restrict__ c1b,
    const float* __restrict__ c2w, const float* __restrict__ c2b,
    const float* __restrict__ c3w, const float* __restrict__ c3b,
    const float* __restrict__ dw,  const float* __restrict__ db,
    const float* __restrict__ trans,
    float* __restrict__ out)
{
    extern __shared__ __align__(16) char smem_raw[];
    SmemLayout* S = (SmemLayout*)smem_raw;

    const int tid = threadIdx.x;

    // ---- prep (block 0): transition matrices into g_M ----
    if (blockIdx.x == 0 && tid < 60) {
        if (tid < 54) {
            const int r = tid / 9, i = tid - r * 9;
            const float* tp = trans + (r * 9 + i) * 10;
            float m = tp[0] * 10.f;
            #pragma unroll
            for (int j = 1; j < 10; j++) m = fmaxf(m, tp[j] * 10.f);
            float e[10];
            float s = 0.f;
            #pragma unroll
            for (int j = 0; j < 10; j++) { e[j] = __expf(tp[j] * 10.f - m); s += e[j]; }
            const float inv = 1.f / s;
            #pragma unroll
            for (int j = 0; j < 10; j++) g_M[r * 100 + i * 10 + j] = e[j] * inv;
        } else {
            const int r = tid - 54;
            #pragma unroll
            for (int j = 0; j < 10; j++) g_M[r * 100 + 90 + j] = (j == 9) ? 1.f : 0.f;
        }
    }

    // ---- stage inputs ----
    {
        const int img0 = blockIdx.x * 2;
        for (int k = tid; k < 784; k += 256) {
            const int im = k / 392, q = k - im * 392;
            const int img = img0 + im;
            const int n = img >> 8, b = img & 255;
            const float2 v = ((const float2*)(seq + ((long)b * NSTEP + n) * 784))[q];
            const int row = q / 14, col2 = q - row * 14;
            *(float2*)&S->img[im][row * IMG_STRIDE + col2 * 2] = v;
        }
    }
    if (tid < 8) {
        S->b1[tid] = c1b[tid];
        #pragma unroll
        for (int t = 0; t < 9; t++) S->w1p[tid * 12 + t] = c1w[tid * 9 + t];
    }
    if (tid < 128) {   // conv2 weights -> oc-pair packed
        const int oc = tid >> 3, ic = tid & 7;
        #pragma unroll
        for (int t = 0; t < 9; t++)
            S->w2pk[((oc >> 1) * 8 + ic) * 20 + t * 2 + (oc & 1)] = c2w[tid * 9 + t];
    }
    if (tid < 16) S->b2[tid] = c2b[tid];
    for (int k = tid; k < 512; k += 256) {   // conv3 weights -> ic-pair packed
        const int oc = k >> 4, ic = k & 15;
        #pragma unroll
        for (int t = 0; t < 9; t++)
            S->w3pk[(((ic >> 1) * 9 + t) * 32 + oc) * 2 + (ic & 1)] = c3w[k * 9 + t];
    }
    if (tid < 32) S->b3[tid] = c3b[tid];
    for (int k = tid; k < 320; k += 256)
        S->dwT[(k & 31) * 10 + (k >> 5)] = dw[k];
    if (tid < 10) S->db[tid] = db[tid];
    __syncthreads();

    // ---- Stage 1: conv1 + relu + pool (FFMA2 packed along pool-dx) ----
    {
        const int g  = tid >> 4;
        const int y  = tid & 15;
        const int im = g >> 3;
        const int c  = g & 7;
        if (y < 13) {
            const float4 w0 = *(const float4*)&S->w1p[c * 12];
            const float4 w1 = *(const float4*)&S->w1p[c * 12 + 4];
            const float w8s = S->w1p[c * 12 + 8];
            const float ws[9] = {w0.x, w0.y, w0.z, w0.w, w1.x, w1.y, w1.z, w1.w, w8s};
            u64t W2[9];
            #pragma unroll
            for (int k = 0; k < 9; k++) PACK2(W2[k], ws[k], ws[k]);
            const float bias = S->b1[c];
            u64t B2; PACK2(B2, bias, bias);
            const int iy = 2 * y;

            float win[4][4];
            #pragma unroll
            for (int r = 0; r < 4; r++) {
                const float2 a = *(const float2*)&S->img[im][(iy + r) * IMG_STRIDE];
                const float2 d = *(const float2*)&S->img[im][(iy + r) * IMG_STRIDE + 2];
                win[r][0] = a.x; win[r][1] = a.y; win[r][2] = d.x; win[r][3] = d.y;
            }
            #pragma unroll
            for (int x = 0; x < 13; x++) {
                u64t a0 = B2, a1 = B2;
                #pragma unroll
                for (int ky = 0; ky < 3; ky++)
                    #pragma unroll
                    for (int kx = 0; kx < 3; kx++) {
                        u64t Pa, Pb;
                        PACK2(Pa, win[ky    ][kx], win[ky    ][kx + 1]);
                        PACK2(Pb, win[ky + 1][kx], win[ky + 1][kx + 1]);
                        FMA2(a0, Pa, W2[ky * 3 + kx], a0);
                        FMA2(a1, Pb, W2[ky * 3 + kx], a1);
                    }
                float v00, v01, v10, v11;
                UNPACK2(v00, v01, a0);
                UNPACK2(v10, v11, a1);
                S->s1p[im][c * S1_PLANE + y * S1_STRIDE + x] =
                    0.25f * (fmaxf(v00, 0.f) + fmaxf(v01, 0.f) +
                             fmaxf(v10, 0.f) + fmaxf(v11, 0.f));
                if (x < 12) {
                    #pragma unroll
                    for (int r = 0; r < 4; r++) {
                        win[r][0] = win[r][2]; win[r][1] = win[r][3];
                        const float2 nb = *(const float2*)
                            &S->img[im][(iy + r) * IMG_STRIDE + 2 * x + 4];
                        win[r][2] = nb.x; win[r][3] = nb.y;
                    }
                }
            }
        }
    }
    __syncthreads();

    // ---- Stage 2: conv2 + relu + pool (FFMA2 packed along oc-pairs) ----
    if (tid < 200) {
        const int im  = tid / 100;
        const int r2  = tid - im * 100;
        const int ocg = r2 / 25;
        const int pos = r2 - ocg * 25;
        const int y = pos / 5, x = pos - y * 5;
        const int iy = 2 * y, ix = 2 * x;
        const int op0 = ocg * 2, op1 = ocg * 2 + 1;

        u64t A[2][4];
        {
            u64t B0, B1;
            PACK2(B0, S->b2[ocg * 4 + 0], S->b2[ocg * 4 + 1]);
            PACK2(B1, S->b2[ocg * 4 + 2], S->b2[ocg * 4 + 3]);
            #pragma unroll
            for (int p = 0; p < 4; p++) { A[0][p] = B0; A[1][p] = B1; }
        }
        #pragma unroll
        for (int ic = 0; ic < 8; ic++) {
            float win[4][4];
            #pragma unroll
            for (int r = 0; r < 4; r++) {
                const float* rowp = &S->s1p[im][ic * S1_PLANE + (iy + r) * S1_STRIDE + ix];
                const float2 u = *(const float2*)rowp;
                const float2 v = *(const float2*)(rowp + 2);
                win[r][0] = u.x; win[r][1] = u.y; win[r][2] = v.x; win[r][3] = v.y;
            }
            const u64t* wq0 = (const u64t*)&S->w2pk[(op0 * 8 + ic) * 20];
            const u64t* wq1 = (const u64t*)&S->w2pk[(op1 * 8 + ic) * 20];
            #pragma unroll
            for (int ky = 0; ky < 3; ky++)
                #pragma unroll
                for (int kx = 0; kx < 3; kx++) {
                    const int k = ky * 3 + kx;
                    const u64t W0 = wq0[k], W1 = wq1[k];
                    u64t D00, D01, D10, D11;
                    PACK2(D00, win[ky    ][kx    ], win[ky    ][kx    ]);
                    PACK2(D01, win[ky    ][kx + 1], win[ky    ][kx + 1]);
                    PACK2(D10, win[ky + 1][kx    ], win[ky + 1][kx    ]);
                    PACK2(D11, win[ky + 1][kx + 1], win[ky + 1][kx + 1]);
                    FMA2(A[0][0], D00, W0, A[0][0]); FMA2(A[1][0], D00, W1, A[1][0]);
                    FMA2(A[0][1], D01, W0, A[0][1]); FMA2(A[1][1], D01, W1, A[1][1]);
                    FMA2(A[0][2], D10, W0, A[0][2]); FMA2(A[1][2], D10, W1, A[1][2]);
                    FMA2(A[0][3], D11, W0, A[0][3]); FMA2(A[1][3], D11, W1, A[1][3]);
                }
        }
        #pragma unroll
        for (int pr = 0; pr < 2; pr++) {
            float e0 = 0.f, e1 = 0.f;
            #pragma unroll
            for (int p = 0; p < 4; p++) {
                float lo, hi;
                UNPACK2(lo, hi, A[pr][p]);
                e0 += fmaxf(lo, 0.f);
                e1 += fmaxf(hi, 0.f);
            }
            S->s2[im][(ocg * 4 + 2 * pr    ) * 25 + pos] = 0.25f * e0;
            S->s2[im][(ocg * 4 + 2 * pr + 1) * 25 + pos] = 0.25f * e1;
        }
    }
    __syncthreads();

    // ---- Stage 3: conv3 + relu + pool. 256 threads (im,oc,pos), ic-pair FFMA2 ----
    {
        const int im  = tid >> 7;
        const int r3  = tid & 127;
        const int oc  = r3 >> 2;
        const int pos = r3 & 3;
        const int dy = pos >> 1, dx = pos & 1;

        u64t acc; PACK2(acc, 0.f, 0.f);
        #pragma unroll
        for (int icp = 0; icp < 8; icp++) {
            const float* pe = &S->s2[im][(2 * icp    ) * 25 + dy * 5 + dx];
            const float* po = &S->s2[im][(2 * icp + 1) * 25 + dy * 5 + dx];
            #pragma unroll
            for (int ky = 0; ky < 3; ky++)
                #pragma unroll
                for (int kx = 0; kx < 3; kx++) {
                    const int k = ky * 3 + kx;
                    const u64t W = *(const u64t*)&S->w3pk[((icp * 9 + k) * 32 + oc) * 2];
                    u64t D; PACK2(D, pe[ky * 5 + kx], po[ky * 5 + kx]);
                    FMA2(acc, D, W, acc);
                }
        }
        float lo, hi;
        UNPACK2(lo, hi, acc);
        float v = fmaxf(lo + hi + S->b3[oc], 0.f);
        v += __shfl_xor_sync(0xffffffffu, v, 1);
        v += __shfl_xor_sync(0xffffffffu, v, 2);
        if (pos == 0) S->s3[im][oc] = 0.25f * v;
    }
    __syncthreads();

    // ---- Dense + softmax + guards: warp 0 ----
    if (tid < 32) {
        if (tid < 20) {
            const int im = tid / 10, j = tid - im * 10;
            float v = S->db[j];
            #pragma unroll
            for (int k = 0; k < 32; k++) v += S->s3[im][k] * S->dwT[k * 10 + j];
            S->logits[im][j] = v;
        }
        __syncwarp();
        if (tid < 20) {
            const int im = tid / 10, j = tid - im * 10;
            float m = S->logits[im][0];
            #pragma unroll
            for (int k = 1; k < 10; k++) m = fmaxf(m, S->logits[im][k]);
            float sum = 0.f;
            #pragma unroll
            for (int k = 0; k < 10; k++) sum += __expf(S->logits[im][k] - m);
            const float p = __expf(S->logits[im][j] - m) / sum;
            S->p2[im][j] = p;
            out[(blockIdx.x * 2 + im) * 10 + j] = p;
        }
        __syncwarp();
        if (tid < 12) {
            const int im = tid / 6, j = tid - im * 6;
            const float* p = S->p2[im];
            float g;
            switch (j) {
                case 0:  g = p[8];         break;
                case 1:  g = p[4] + p[6];  break;
                case 2:  g = p[0] + p[2];  break;
                case 3:  g = p[7] + p[9];  break;
                case 4:  g = p[5];         break;
                default: g = p[1] + p[3];  break;
            }
            const int img = blockIdx.x * 2 + im;
            out[GUARD_BASE + img * 6 + j] = g;
            g_guardT[img & 255][(img >> 8) * 6 + j] = g;   // transposed copy
        }
    }
}

// ---------------------------------------------------------------------------
// SFA: 32 blocks x 8 warps; M staged to smem once per block (cuts the 60
// scattered cold LDGs per lane that dominated the 9.7us runtime).
// ---------------------------------------------------------------------------
__global__ __launch_bounds__(256) void sfa_kernel(float* __restrict__ out)
{
    __shared__ float sM[600];
    __shared__ float s_g[8][NSTEP * 6];

    const int tid  = threadIdx.x;
    const int w    = tid >> 5;
    const int lane = tid & 31;
    const int b    = blockIdx.x * 8 + w;

    // coalesced one-time staging of the transition matrices
    for (int k = tid; k < 600; k += 256) sM[k] = g_M[k];

    #pragma unroll
    for (int k = lane; k < NSTEP * 6; k += 32)
        s_g[w][k] = g_guardT[b][k];
    __syncthreads();

    const int jj = (lane < 10) ? lane : 0;
    float Mr[6][10];
    #pragma unroll
    for (int r = 0; r < 6; r++)
        #pragma unroll
        for (int i = 0; i < 10; i++)
            Mr[r][i] = sM[r * 100 + i * 10 + jj];

    float st = (lane == 0) ? 1.f : 0.f;
    for (int n = 0; n < NSTEP; n++) {
        const float g0 = s_g[w][n*6+0], g1 = s_g[w][n*6+1], g2 = s_g[w][n*6+2];
        const float g3 = s_g[w][n*6+3], g4 = s_g[w][n*6+4], g5 = s_g[w][n*6+5];
        float a = 0.f;
        #pragma unroll
        for (int i = 0; i < 10; i++) {
            const float si = __shfl_sync(0xffffffff, st, i);
            const float mij = g0 * Mr[0][i] + g1 * Mr[1][i] + g2 * Mr[2][i]
                            + g3 * Mr[3][i] + g4 * Mr[4][i] + g5 * Mr[5][i];
            a += si * mij;
        }
        st = a;
    }
    if (lane < 10) out[STATE_BASE + b * 10 + lane] = st;
}

// ---------------------------------------------------------------------------
extern "C" void kernel_launch(void* const* d_in, const int* in_sizes, int n_in,
                              void* d_out, int out_size)
{
    const float* seq   = (const float*)d_in[0];
    const float* c1w   = (const float*)d_in[1];
    const float* c1b   = (const float*)d_in[2];
    const float* c2w   = (const float*)d_in[3];
    const float* c2b   = (const float*)d_in[4];
    const float* c3w   = (const float*)d_in[5];
    const float* c3b   = (const float*)d_in[6];
    const float* dw    = (const float*)d_in[7];
    const float* db    = (const float*)d_in[8];
    const float* trans = (const float*)d_in[9];
    float* out = (float*)d_out;

    const int smem_bytes = (int)sizeof(SmemLayout);
    cudaFuncSetAttribute(cnn_kernel, cudaFuncAttributeMaxDynamicSharedMemorySize,
                         smem_bytes);

    cnn_kernel<<<NIMG / 2, 256, smem_bytes>>>(seq, c1w, c1b, c2w, c2b,
                                              c3w, c3b, dw, db, trans, out);
    sfa_kernel<<<BATCH / 8, 256>>>(out);
}

// round 13
// speedup vs baseline: 1.5400x; 1.0125x over previous
#include <cuda_runtime.h>
#include <math.h>

#define BATCH 256
#define NSTEP 32
#define NIMG  (BATCH*NSTEP)
#define NBLK  (NIMG/2)        // 4096
#define NSFA  32              // last 32 blocks run the recurrence

#define GUARD_BASE 81920
#define STATE_BASE 131072

#define IMG_STRIDE 30
#define S1_STRIDE  22
#define S1_PLANE   (13 * S1_STRIDE)

typedef unsigned long long u64t;

// packed f32x2 helpers (sm_103a FFMA2 path)
#define PACK2(d, lo, hi) \
    asm("mov.b64 %0, {%1, %2};" : "=l"(d) : "r"(__float_as_uint(lo)), "r"(__float_as_uint(hi)))
#define FMA2(d, a, b, c) \
    asm("fma.rn.f32x2 %0, %1, %2, %3;" : "=l"(d) : "l"(a), "l"(b), "l"(c))
#define UNPACK2(lo, hi, s) do { unsigned _ulo, _uhi; \
    asm("mov.b64 {%0, %1}, %2;" : "=r"(_ulo), "=r"(_uhi) : "l"(s)); \
    lo = __uint_as_float(_ulo); hi = __uint_as_float(_uhi); } while (0)

__device__ float g_M[600];                 // (6,10,10) transition matrices
__device__ float g_guardT[BATCH][NSTEP*6]; // transposed guards for sfa
__device__ int   g_done  = 0;              // cnn-blocks-finished counter
__device__ int   g_done2 = 0;              // sfa-blocks-finished counter

struct SmemLayout {
    float img[2][28 * IMG_STRIDE];
    float s1p[2][8 * S1_PLANE];
    float s2[2][400];
    float s3[2][32];
    float w1p[8 * 12];  float b1[8];
    float w2pk[8 * 8 * 20];      // [ocpair][ic][k*2+half], padded to 20
    float b2[16];
    float w3pk[8 * 9 * 32 * 2];  // [icpair][k][oc] float2 (ic even, ic odd)
    float b3[32];
    float dwT[32 * 10]; float db[10];
    float logits[2][10]; float p2[2][10];
};

// ---------------------------------------------------------------------------
// Fused CNN (round-6 proven) + in-kernel SFA tail on the last 32 blocks.
// ---------------------------------------------------------------------------
__global__ __launch_bounds__(256, 4) void cnn_kernel(
    const float* __restrict__ seq,
    const float* __restrict__ c1w, const float* __restrict__ c1b,
    const float* __restrict__ c2w, const float* __restrict__ c2b,
    const float* __restrict__ c3w, const float* __restrict__ c3b,
    const float* __restrict__ dw,  const float* __restrict__ db,
    const float* __restrict__ trans,
    float* __restrict__ out)
{
    extern __shared__ __align__(16) char smem_raw[];
    SmemLayout* S = (SmemLayout*)smem_raw;

    const int tid = threadIdx.x;

    // ---- prep (block 0): transition matrices into g_M ----
    if (blockIdx.x == 0 && tid < 60) {
        if (tid < 54) {
            const int r = tid / 9, i = tid - r * 9;
            const float* tp = trans + (r * 9 + i) * 10;
            float m = tp[0] * 10.f;
            #pragma unroll
            for (int j = 1; j < 10; j++) m = fmaxf(m, tp[j] * 10.f);
            float e[10];
            float s = 0.f;
            #pragma unroll
            for (int j = 0; j < 10; j++) { e[j] = __expf(tp[j] * 10.f - m); s += e[j]; }
            const float inv = 1.f / s;
            #pragma unroll
            for (int j = 0; j < 10; j++) g_M[r * 100 + i * 10 + j] = e[j] * inv;
        } else {
            const int r = tid - 54;
            #pragma unroll
            for (int j = 0; j < 10; j++) g_M[r * 100 + 90 + j] = (j == 9) ? 1.f : 0.f;
        }
    }

    // ---- stage inputs ----
    {
        const int img0 = blockIdx.x * 2;
        for (int k = tid; k < 784; k += 256) {
            const int im = k / 392, q = k - im * 392;
            const int img = img0 + im;
            const int n = img >> 8, b = img & 255;
            const float2 v = ((const float2*)(seq + ((long)b * NSTEP + n) * 784))[q];
            const int row = q / 14, col2 = q - row * 14;
            *(float2*)&S->img[im][row * IMG_STRIDE + col2 * 2] = v;
        }
    }
    if (tid < 8) {
        S->b1[tid] = c1b[tid];
        #pragma unroll
        for (int t = 0; t < 9; t++) S->w1p[tid * 12 + t] = c1w[tid * 9 + t];
    }
    if (tid < 128) {   // conv2 weights -> oc-pair packed
        const int oc = tid >> 3, ic = tid & 7;
        #pragma unroll
        for (int t = 0; t < 9; t++)
            S->w2pk[((oc >> 1) * 8 + ic) * 20 + t * 2 + (oc & 1)] = c2w[tid * 9 + t];
    }
    if (tid < 16) S->b2[tid] = c2b[tid];
    for (int k = tid; k < 512; k += 256) {   // conv3 weights -> ic-pair packed
        const int oc = k >> 4, ic = k & 15;
        #pragma unroll
        for (int t = 0; t < 9; t++)
            S->w3pk[(((ic >> 1) * 9 + t) * 32 + oc) * 2 + (ic & 1)] = c3w[k * 9 + t];
    }
    if (tid < 32) S->b3[tid] = c3b[tid];
    for (int k = tid; k < 320; k += 256)
        S->dwT[(k & 31) * 10 + (k >> 5)] = dw[k];
    if (tid < 10) S->db[tid] = db[tid];
    __syncthreads();

    // ---- Stage 1: conv1 + relu + pool (FFMA2 packed along pool-dx) ----
    {
        const int g  = tid >> 4;
        const int y  = tid & 15;
        const int im = g >> 3;
        const int c  = g & 7;
        if (y < 13) {
            const float4 w0 = *(const float4*)&S->w1p[c * 12];
            const float4 w1 = *(const float4*)&S->w1p[c * 12 + 4];
            const float w8s = S->w1p[c * 12 + 8];
            const float ws[9] = {w0.x, w0.y, w0.z, w0.w, w1.x, w1.y, w1.z, w1.w, w8s};
            u64t W2[9];
            #pragma unroll
            for (int k = 0; k < 9; k++) PACK2(W2[k], ws[k], ws[k]);
            const float bias = S->b1[c];
            u64t B2; PACK2(B2, bias, bias);
            const int iy = 2 * y;

            float win[4][4];
            #pragma unroll
            for (int r = 0; r < 4; r++) {
                const float2 a = *(const float2*)&S->img[im][(iy + r) * IMG_STRIDE];
                const float2 d = *(const float2*)&S->img[im][(iy + r) * IMG_STRIDE + 2];
                win[r][0] = a.x; win[r][1] = a.y; win[r][2] = d.x; win[r][3] = d.y;
            }
            #pragma unroll
            for (int x = 0; x < 13; x++) {
                u64t a0 = B2, a1 = B2;
                #pragma unroll
                for (int ky = 0; ky < 3; ky++)
                    #pragma unroll
                    for (int kx = 0; kx < 3; kx++) {
                        u64t Pa, Pb;
                        PACK2(Pa, win[ky    ][kx], win[ky    ][kx + 1]);
                        PACK2(Pb, win[ky + 1][kx], win[ky + 1][kx + 1]);
                        FMA2(a0, Pa, W2[ky * 3 + kx], a0);
                        FMA2(a1, Pb, W2[ky * 3 + kx], a1);
                    }
                float v00, v01, v10, v11;
                UNPACK2(v00, v01, a0);
                UNPACK2(v10, v11, a1);
                S->s1p[im][c * S1_PLANE + y * S1_STRIDE + x] =
                    0.25f * (fmaxf(v00, 0.f) + fmaxf(v01, 0.f) +
                             fmaxf(v10, 0.f) + fmaxf(v11, 0.f));
                if (x < 12) {
                    #pragma unroll
                    for (int r = 0; r < 4; r++) {
                        win[r][0] = win[r][2]; win[r][1] = win[r][3];
                        const float2 nb = *(const float2*)
                            &S->img[im][(iy + r) * IMG_STRIDE + 2 * x + 4];
                        win[r][2] = nb.x; win[r][3] = nb.y;
                    }
                }
            }
        }
    }
    __syncthreads();

    // ---- Stage 2: conv2 + relu + pool (FFMA2 packed along oc-pairs) ----
    if (tid < 200) {
        const int im  = tid / 100;
        const int r2  = tid - im * 100;
        const int ocg = r2 / 25;
        const int pos = r2 - ocg * 25;
        const int y = pos / 5, x = pos - y * 5;
        const int iy = 2 * y, ix = 2 * x;
        const int op0 = ocg * 2, op1 = ocg * 2 + 1;

        u64t A[2][4];
        {
            u64t B0, B1;
            PACK2(B0, S->b2[ocg * 4 + 0], S->b2[ocg * 4 + 1]);
            PACK2(B1, S->b2[ocg * 4 + 2], S->b2[ocg * 4 + 3]);
            #pragma unroll
            for (int p = 0; p < 4; p++) { A[0][p] = B0; A[1][p] = B1; }
        }
        #pragma unroll
        for (int ic = 0; ic < 8; ic++) {
            float win[4][4];
            #pragma unroll
            for (int r = 0; r < 4; r++) {
                const float* rowp = &S->s1p[im][ic * S1_PLANE + (iy + r) * S1_STRIDE + ix];
                const float2 u = *(const float2*)rowp;
                const float2 v = *(const float2*)(rowp + 2);
                win[r][0] = u.x; win[r][1] = u.y; win[r][2] = v.x; win[r][3] = v.y;
            }
            const u64t* wq0 = (const u64t*)&S->w2pk[(op0 * 8 + ic) * 20];
            const u64t* wq1 = (const u64t*)&S->w2pk[(op1 * 8 + ic) * 20];
            #pragma unroll
            for (int ky = 0; ky < 3; ky++)
                #pragma unroll
                for (int kx = 0; kx < 3; kx++) {
                    const int k = ky * 3 + kx;
                    const u64t W0 = wq0[k], W1 = wq1[k];
                    u64t D00, D01, D10, D11;
                    PACK2(D00, win[ky    ][kx    ], win[ky    ][kx    ]);
                    PACK2(D01, win[ky    ][kx + 1], win[ky    ][kx + 1]);
                    PACK2(D10, win[ky + 1][kx    ], win[ky + 1][kx    ]);
                    PACK2(D11, win[ky + 1][kx + 1], win[ky + 1][kx + 1]);
                    FMA2(A[0][0], D00, W0, A[0][0]); FMA2(A[1][0], D00, W1, A[1][0]);
                    FMA2(A[0][1], D01, W0, A[0][1]); FMA2(A[1][1], D01, W1, A[1][1]);
                    FMA2(A[0][2], D10, W0, A[0][2]); FMA2(A[1][2], D10, W1, A[1][2]);
                    FMA2(A[0][3], D11, W0, A[1 - 1][3]); FMA2(A[1][3], D11, W1, A[1][3]);
                }
        }
        #pragma unroll
        for (int pr = 0; pr < 2; pr++) {
            float e0 = 0.f, e1 = 0.f;
            #pragma unroll
            for (int p = 0; p < 4; p++) {
                float lo, hi;
                UNPACK2(lo, hi, A[pr][p]);
                e0 += fmaxf(lo, 0.f);
                e1 += fmaxf(hi, 0.f);
            }
            S->s2[im][(ocg * 4 + 2 * pr    ) * 25 + pos] = 0.25f * e0;
            S->s2[im][(ocg * 4 + 2 * pr + 1) * 25 + pos] = 0.25f * e1;
        }
    }
    __syncthreads();

    // ---- Stage 3: conv3 + relu + pool. 256 threads (im,oc,pos), ic-pair FFMA2 ----
    {
        const int im  = tid >> 7;
        const int r3  = tid & 127;
        const int oc  = r3 >> 2;
        const int pos = r3 & 3;
        const int dy = pos >> 1, dx = pos & 1;

        u64t acc; PACK2(acc, 0.f, 0.f);
        #pragma unroll
        for (int icp = 0; icp < 8; icp++) {
            const float* pe = &S->s2[im][(2 * icp    ) * 25 + dy * 5 + dx];
            const float* po = &S->s2[im][(2 * icp + 1) * 25 + dy * 5 + dx];
            #pragma unroll
            for (int ky = 0; ky < 3; ky++)
                #pragma unroll
                for (int kx = 0; kx < 3; kx++) {
                    const int k = ky * 3 + kx;
                    const u64t W = *(const u64t*)&S->w3pk[((icp * 9 + k) * 32 + oc) * 2];
                    u64t D; PACK2(D, pe[ky * 5 + kx], po[ky * 5 + kx]);
                    FMA2(acc, D, W, acc);
                }
        }
        float lo, hi;
        UNPACK2(lo, hi, acc);
        float v = fmaxf(lo + hi + S->b3[oc], 0.f);
        v += __shfl_xor_sync(0xffffffffu, v, 1);
        v += __shfl_xor_sync(0xffffffffu, v, 2);
        if (pos == 0) S->s3[im][oc] = 0.25f * v;
    }
    __syncthreads();

    // ---- Dense + softmax + guards: warp 0 ----
    if (tid < 32) {
        if (tid < 20) {
            const int im = tid / 10, j = tid - im * 10;
            float v = S->db[j];
            #pragma unroll
            for (int k = 0; k < 32; k++) v += S->s3[im][k] * S->dwT[k * 10 + j];
            S->logits[im][j] = v;
        }
        __syncwarp();
        if (tid < 20) {
            const int im = tid / 10, j = tid - im * 10;
            float m = S->logits[im][0];
            #pragma unroll
            for (int k = 1; k < 10; k++) m = fmaxf(m, S->logits[im][k]);
            float sum = 0.f;
            #pragma unroll
            for (int k = 0; k < 10; k++) sum += __expf(S->logits[im][k] - m);
            const float p = __expf(S->logits[im][j] - m) / sum;
            S->p2[im][j] = p;
            out[(blockIdx.x * 2 + im) * 10 + j] = p;
        }
        __syncwarp();
        if (tid < 12) {
            const int im = tid / 6, j = tid - im * 6;
            const float* p = S->p2[im];
            float g;
            switch (j) {
                case 0:  g = p[8];         break;
                case 1:  g = p[4] + p[6];  break;
                case 2:  g = p[0] + p[2];  break;
                case 3:  g = p[7] + p[9];  break;
                case 4:  g = p[5];         break;
                default: g = p[1] + p[3];  break;
            }
            const int img = blockIdx.x * 2 + im;
            out[GUARD_BASE + img * 6 + j] = g;
            g_guardT[img & 255][(img >> 8) * 6 + j] = g;   // transposed copy
        }
    }

    // ---- signal completion ----
    __syncthreads();
    if (tid == 0) {
        __threadfence();                       // publish guards (+ g_M from blk 0)
        atomicAdd(&g_done, 1);
    }

    // ---- SFA tail: last 32 blocks (scheduled last -> minimal spin) ----
    if (blockIdx.x >= NBLK - NSFA) {
        if (tid == 0) {
            while (*(volatile int*)&g_done < NBLK) __nanosleep(128);
        }
        __syncthreads();
        __threadfence();                       // acquire guards

        // repurpose dynamic smem (cnn phase is over for this block)
        float* sM  = (float*)smem_raw;         // 600
        float* s_g = sM + 600;                 // 8 * 192

        const int w    = tid >> 5;
        const int lane = tid & 31;
        const int b    = (int)(blockIdx.x - (NBLK - NSFA)) * 8 + w;

        for (int k = tid; k < 600; k += 256) sM[k] = g_M[k];
        #pragma unroll
        for (int k = lane; k < NSTEP * 6; k += 32)
            s_g[w * (NSTEP * 6) + k] = g_guardT[b][k];
        __syncthreads();

        const int jj = (lane < 10) ? lane : 0;
        float Mr[6][10];
        #pragma unroll
        for (int r = 0; r < 6; r++)
            #pragma unroll
            for (int i = 0; i < 10; i++)
                Mr[r][i] = sM[r * 100 + i * 10 + jj];

        const float* gw = &s_g[w * (NSTEP * 6)];
        float st = (lane == 0) ? 1.f : 0.f;
        for (int n = 0; n < NSTEP; n++) {
            const float g0 = gw[n*6+0], g1 = gw[n*6+1], g2 = gw[n*6+2];
            const float g3 = gw[n*6+3], g4 = gw[n*6+4], g5 = gw[n*6+5];
            float a = 0.f;
            #pragma unroll
            for (int i = 0; i < 10; i++) {
                const float si = __shfl_sync(0xffffffff, st, i);
                const float mij = g0 * Mr[0][i] + g1 * Mr[1][i] + g2 * Mr[2][i]
                                + g3 * Mr[3][i] + g4 * Mr[4][i] + g5 * Mr[5][i];
                a += si * mij;
            }
            st = a;
        }
        if (lane < 10) out[STATE_BASE + b * 10 + lane] = st;

        // reset counters for the next graph replay
        __syncthreads();
        if (tid == 0) {
            const int t2 = atomicAdd(&g_done2, 1);
            if (t2 == NSFA - 1) {
                g_done  = 0;
                g_done2 = 0;
                __threadfence();
            }
        }
    }
}

// ---------------------------------------------------------------------------
extern "C" void kernel_launch(void* const* d_in, const int* in_sizes, int n_in,
                              void* d_out, int out_size)
{
    const float* seq   = (const float*)d_in[0];
    const float* c1w   = (const float*)d_in[1];
    const float* c1b   = (const float*)d_in[2];
    const float* c2w   = (const float*)d_in[3];
    const float* c2b   = (const float*)d_in[4];
    const float* c3w   = (const float*)d_in[5];
    const float* c3b   = (const float*)d_in[6];
    const float* dw    = (const float*)d_in[7];
    const float* db    = (const float*)d_in[8];
    const float* trans = (const float*)d_in[9];
    float* out = (float*)d_out;

    const int smem_bytes = (int)sizeof(SmemLayout);
    cudaFuncSetAttribute(cnn_kernel, cudaFuncAttributeMaxDynamicSharedMemorySize,
                         smem_bytes);

    cnn_kernel<<<NBLK, 256, smem_bytes>>>(seq, c1w, c1b, c2w, c2b,
                                          c3w, c3b, dw, db, trans, out);
}